// round 2
// baseline (speedup 1.0000x reference)
#include <cuda_runtime.h>
#include <cuda_bf16.h>
#include <stdint.h>
#include <stddef.h>

#define BDIM 4096
#define INDIM 2048
#define HDIM 2048
#define KDIM 4096   // IN + H
#define NDIM 8192   // 4 * H

// ---------------- scratch (static device globals; no runtime alloc) ----------------
__device__ __nv_bfloat16 g_Ahi[(size_t)BDIM * KDIM];
__device__ __nv_bfloat16 g_Alo[(size_t)BDIM * KDIM];
__device__ __nv_bfloat16 g_Bhi[(size_t)NDIM * KDIM];
__device__ __nv_bfloat16 g_Blo[(size_t)NDIM * KDIM];
__device__ float        g_gates[(size_t)BDIM * NDIM];

// ---------------- PTX helpers ----------------
__device__ __forceinline__ uint32_t smem_u32(const void* p) {
    uint32_t a;
    asm("{ .reg .u64 t; cvta.to.shared.u64 t, %1; cvt.u32.u64 %0, t; }" : "=r"(a) : "l"(p));
    return a;
}
#define SWZ128(o) ((o) ^ (((o) >> 3) & 0x70))

// legacy tensor path (compute_103-safe)
#define LDSM4(r, addr) \
    asm volatile("ldmatrix.sync.aligned.m8n8.x4.shared.b16 {%0,%1,%2,%3}, [%4];" \
        : "=r"((r)[0]), "=r"((r)[1]), "=r"((r)[2]), "=r"((r)[3]) : "r"(addr))

#define MMA16816(d, a, b0, b1) \
    asm volatile("mma.sync.aligned.m16n8k16.row.col.f32.bf16.bf16.f32 " \
        "{%0,%1,%2,%3}, {%4,%5,%6,%7}, {%8,%9}, {%0,%1,%2,%3};" \
        : "+f"((d)[0]), "+f"((d)[1]), "+f"((d)[2]), "+f"((d)[3]) \
        : "r"((a)[0]), "r"((a)[1]), "r"((a)[2]), "r"((a)[3]), "r"(b0), "r"(b1))

#define CP_ASYNC16(s, g) \
    asm volatile("cp.async.cg.shared.global [%0], [%1], 16;" :: "r"(s), "l"(g))
#define CP_COMMIT() asm volatile("cp.async.commit_group;" ::: "memory")
#define CP_WAIT0()  asm volatile("cp.async.wait_group 0;" ::: "memory")
#define CP_WAIT1()  asm volatile("cp.async.wait_group 1;" ::: "memory")

#if defined(__CUDA_ARCH_FEAT_SM103_ALL)
// ---- tcgen05 helpers (only compiled when an sm_103a gencode pass exists) ----
__device__ __forceinline__ bool elect_one() {
    uint32_t pred;
    asm volatile("{ .reg .pred p; elect.sync _|p, 0xFFFFFFFF; selp.b32 %0, 1, 0, p; }" : "=r"(pred));
    return pred != 0;
}
#define MBARRIER_INIT(addr, cnt) \
    asm volatile("mbarrier.init.shared.b64 [%0], %1;" :: "r"((uint32_t)(addr)), "r"((uint32_t)(cnt)) : "memory")
#define MBARRIER_INVAL(addr) \
    asm volatile("mbarrier.inval.shared.b64 [%0];" :: "r"((uint32_t)(addr)) : "memory")
#define MBARRIER_WAIT_PARITY(mbar_smem_addr, phase_parity) do { \
    uint32_t _mbar = (uint32_t)(mbar_smem_addr); \
    uint32_t _parity = (uint32_t)(phase_parity); \
    uint32_t _done; \
    asm volatile( \
        "{\n\t.reg .pred p;\n\tmbarrier.try_wait.parity.acquire.cta.shared::cta.b64 p, [%1], %2;\n\t" \
        "selp.b32 %0, 1, 0, p;\n\t}" \
        : "=r"(_done) : "r"(_mbar), "r"(_parity) : "memory"); \
    if (!_done) { \
        asm volatile( \
            "{\n\t.reg .pred P1;\n\tWAIT_LOOP_%=:\n\t" \
            "mbarrier.try_wait.parity.acquire.cta.shared::cta.b64 P1, [%0], %1, 0x989680;\n\t" \
            "@P1 bra.uni WAIT_DONE_%=;\n\tbra.uni WAIT_LOOP_%=;\n\tWAIT_DONE_%=:\n\t}" \
            :: "r"(_mbar), "r"(_parity) : "memory"); \
    } \
} while(0)
#define TCGEN05_ALLOC(smem_addr, nCols) \
    asm volatile("tcgen05.alloc.cta_group::1.sync.aligned.shared::cta.b32 [%0], %1;" \
                 :: "r"((uint32_t)(smem_addr)), "r"((uint32_t)(nCols)) : "memory")
#define TCGEN05_RELINQUISH() \
    asm volatile("tcgen05.relinquish_alloc_permit.cta_group::1.sync.aligned;")
#define TCGEN05_DEALLOC(tmem_addr, nCols) \
    asm volatile("tcgen05.dealloc.cta_group::1.sync.aligned.b32 %0, %1;" \
                 :: "r"(tmem_addr), "r"((uint32_t)(nCols)))
#define TCGEN05_COMMIT(mbar) \
    asm volatile("tcgen05.commit.cta_group::1.mbarrier::arrive::one.shared::cluster.b64 [%0];" \
                 :: "r"((uint32_t)(mbar)) : "memory")
#define TCGEN05_FENCE_AFTER()  asm volatile("tcgen05.fence::after_thread_sync;" ::: "memory")
#define TCGEN05_FENCE_BEFORE() asm volatile("tcgen05.fence::before_thread_sync;" ::: "memory")
#define TCGEN05_WAIT_LD()      asm volatile("tcgen05.wait::ld.sync.aligned;" ::: "memory")
#define FENCE_PROXY_ASYNC()    asm volatile("fence.proxy.async.shared::cta;" ::: "memory")
#define TCGEN05_LD_32X32B_X32(r, tmem_addr) \
    asm volatile( \
        "tcgen05.ld.sync.aligned.32x32b.x32.b32 " \
        "{%0, %1, %2, %3, %4, %5, %6, %7, " \
        " %8, %9, %10, %11, %12, %13, %14, %15, " \
        " %16, %17, %18, %19, %20, %21, %22, %23, " \
        " %24, %25, %26, %27, %28, %29, %30, %31}, [%32];" \
        : "=r"((r)[0]),  "=r"((r)[1]),  "=r"((r)[2]),  "=r"((r)[3]), \
          "=r"((r)[4]),  "=r"((r)[5]),  "=r"((r)[6]),  "=r"((r)[7]), \
          "=r"((r)[8]),  "=r"((r)[9]),  "=r"((r)[10]), "=r"((r)[11]), \
          "=r"((r)[12]), "=r"((r)[13]), "=r"((r)[14]), "=r"((r)[15]), \
          "=r"((r)[16]), "=r"((r)[17]), "=r"((r)[18]), "=r"((r)[19]), \
          "=r"((r)[20]), "=r"((r)[21]), "=r"((r)[22]), "=r"((r)[23]), \
          "=r"((r)[24]), "=r"((r)[25]), "=r"((r)[26]), "=r"((r)[27]), \
          "=r"((r)[28]), "=r"((r)[29]), "=r"((r)[30]), "=r"((r)[31]) \
        : "r"(tmem_addr))

__device__ __forceinline__ uint64_t sdesc(uint32_t addr) {
    const uint64_t base = (uint64_t(2) << 61) | (uint64_t(1) << 46) |
                          (uint64_t(64) << 32) | (uint64_t(1) << 16);
    return base | ((uint64_t)(addr >> 4) & 0x3FFF);
}
#define MMA_IDESC 0x8400490u
__device__ __forceinline__ void mma_bf16_ss(uint32_t d, uint64_t ad, uint64_t bd, uint32_t en) {
    asm volatile(
        "{\n\t.reg .pred p;\n\tsetp.ne.u32 p, %4, 0;\n\t"
        "tcgen05.mma.cta_group::1.kind::f16 [%0], %1, %2, %3, {%5, %5, %5, %5}, p;\n\t}"
        :: "r"(d), "l"(ad), "l"(bd), "r"(MMA_IDESC), "r"(en), "r"(0u)
        : "memory");
}
#endif  // __CUDA_ARCH_FEAT_SM103_ALL

// ---------------- Kernel 1: build A (= [x | h]) as bf16 hi/lo ----------------
__global__ void prep_a_kernel(const float* __restrict__ x, const float* __restrict__ h) {
    size_t gid = (size_t)blockIdx.x * blockDim.x + threadIdx.x;
    size_t e = gid * 4;
    if (e >= (size_t)BDIM * KDIM) return;
    int b = (int)(e >> 12);        // / 4096
    int k = (int)(e & 4095);
    const float* src = (k < INDIM) ? (x + (size_t)b * INDIM + k)
                                   : (h + (size_t)b * HDIM + (k - INDIM));
    float4 v = *reinterpret_cast<const float4*>(src);
    float vv[4] = {v.x, v.y, v.z, v.w};
    __nv_bfloat16 hi[4], lo[4];
#pragma unroll
    for (int i = 0; i < 4; i++) {
        hi[i] = __float2bfloat16(vv[i]);
        lo[i] = __float2bfloat16(vv[i] - __bfloat162float(hi[i]));
    }
    __nv_bfloat162* ph = reinterpret_cast<__nv_bfloat162*>(g_Ahi + e);
    __nv_bfloat162* pl = reinterpret_cast<__nv_bfloat162*>(g_Alo + e);
    ph[0] = __nv_bfloat162(hi[0], hi[1]); ph[1] = __nv_bfloat162(hi[2], hi[3]);
    pl[0] = __nv_bfloat162(lo[0], lo[1]); pl[1] = __nv_bfloat162(lo[2], lo[3]);
}

// ---------------- Kernel 2: transpose + convert weights into B[n][k] hi/lo ----------------
__global__ void prep_w_kernel(
    const float* __restrict__ w0, const float* __restrict__ w1,
    const float* __restrict__ w2, const float* __restrict__ w3,
    const float* __restrict__ w4, const float* __restrict__ w5,
    const float* __restrict__ w6, const float* __restrict__ w7) {
    __shared__ float t[64][33];
    int z = blockIdx.z;
    const float* w;
    switch (z) {
        case 0: w = w0; break; case 1: w = w1; break;
        case 2: w = w2; break; case 3: w = w3; break;
        case 4: w = w4; break; case 5: w = w5; break;
        case 6: w = w6; break; default: w = w7; break;
    }
    int k0 = blockIdx.x * 64;
    int j0 = blockIdx.y * 32;
    int tx = threadIdx.x, ty = threadIdx.y;
#pragma unroll
    for (int i = 0; i < 8; i++) {
        int r = ty + i * 8;
        t[r][tx] = w[(size_t)(k0 + r) * 2048 + j0 + tx];
    }
    __syncthreads();
    int gate = z & 3;
    int koff = (z >> 2) * 2048;
#pragma unroll
    for (int i = 0; i < 4; i++) {
        int jj = ty + i * 8;
        float v0 = t[2 * tx][jj];
        float v1 = t[2 * tx + 1][jj];
        __nv_bfloat16 h0 = __float2bfloat16(v0);
        __nv_bfloat16 h1 = __float2bfloat16(v1);
        __nv_bfloat16 l0 = __float2bfloat16(v0 - __bfloat162float(h0));
        __nv_bfloat16 l1 = __float2bfloat16(v1 - __bfloat162float(h1));
        size_t n = (size_t)gate * 2048 + j0 + jj;
        size_t off = n * KDIM + koff + k0 + 2 * tx;
        *reinterpret_cast<__nv_bfloat162*>(g_Bhi + off) = __nv_bfloat162(h0, h1);
        *reinterpret_cast<__nv_bfloat162*>(g_Blo + off) = __nv_bfloat162(l0, l1);
    }
}

// ---------------- Kernel 3: GEMM  gates = A(4096x4096) * B^T(8192x4096) ----------------
#define TILE_M 128
#define TILE_N 256
#define TILE_K 64
#define SM_TMEM 0
#define SM_MBAR 16
#define SM_TILES 1024
#define ST_A_HI 0
#define ST_A_LO (16 * 1024)
#define ST_B_HI (32 * 1024)
#define ST_B_LO (64 * 1024)
#define STAGE_BYTES (96 * 1024)
#define GEMM_SMEM (1024 + 2 * STAGE_BYTES)
#define K_ITERS (KDIM / TILE_K)   // 64

template <int ROWS>
__device__ __forceinline__ void load_tile(const __nv_bfloat16* __restrict__ g,
                                          int row0, int k0, char* s, int tid) {
#pragma unroll
    for (int i = 0; i < ROWS * 8 / 256; i++) {
        int q = tid + i * 256;
        int r = q >> 3, c = q & 7;
        uint4 v = *reinterpret_cast<const uint4*>(g + (size_t)(row0 + r) * KDIM + k0 + c * 8);
        uint32_t off = (uint32_t)(r * 128 + c * 16);
        *reinterpret_cast<uint4*>(s + SWZ128(off)) = v;
    }
}

template <int ROWS>
__device__ __forceinline__ void load_tile_async(const __nv_bfloat16* __restrict__ g,
                                                int row0, int k0, uint32_t sdst, int tid) {
#pragma unroll
    for (int i = 0; i < ROWS * 8 / 256; i++) {
        int q = tid + i * 256;
        int r = q >> 3, c = q & 7;
        const void* gp = g + (size_t)(row0 + r) * KDIM + k0 + c * 8;
        uint32_t off = (uint32_t)(r * 128 + c * 16);
        CP_ASYNC16(sdst + SWZ128(off), gp);
    }
}

__global__ __launch_bounds__(256, 1) void gemm_kernel() {
    extern __shared__ char smem[];
    uint32_t sbase = smem_u32(smem);
    int tid = threadIdx.x;
    int wid = tid >> 5, lane = tid & 31;
    int mt = blockIdx.x & 31;       // M fast-varying: a wave shares B tiles
    int nt = blockIdx.x >> 5;
    int m0 = mt * TILE_M, n0 = nt * TILE_N;

#if defined(__CUDA_ARCH_FEAT_SM103_ALL)
    // ================= tcgen05 path =================
    if (wid == 0) {
        TCGEN05_ALLOC(sbase + SM_TMEM, 256);
        TCGEN05_RELINQUISH();
    }
    if (tid == 0) {
        MBARRIER_INIT(sbase + SM_MBAR, 1);
        MBARRIER_INIT(sbase + SM_MBAR + 8, 1);
    }
    __syncthreads();
    uint32_t tmem;
    asm volatile("ld.shared.b32 %0, [%1];" : "=r"(tmem) : "r"(sbase + SM_TMEM));

    bool ismma = false;
    if (wid == 0) ismma = elect_one();

    for (int it = 0; it < K_ITERS; ++it) {
        int s = it & 1;
        int n = it >> 1;
        char* stile = smem + SM_TILES + s * STAGE_BYTES;
        uint32_t stile_u = sbase + SM_TILES + s * STAGE_BYTES;
        if (n >= 1) MBARRIER_WAIT_PARITY(sbase + SM_MBAR + 8 * s, (n - 1) & 1);
        int k0 = it * TILE_K;
        load_tile<128>(g_Ahi, m0, k0, stile + ST_A_HI, tid);
        load_tile<128>(g_Alo, m0, k0, stile + ST_A_LO, tid);
        load_tile<256>(g_Bhi, n0, k0, stile + ST_B_HI, tid);
        load_tile<256>(g_Blo, n0, k0, stile + ST_B_LO, tid);
        FENCE_PROXY_ASYNC();
        __syncthreads();
        if (ismma) {
            uint64_t dAhi = sdesc(stile_u + ST_A_HI);
            uint64_t dAlo = sdesc(stile_u + ST_A_LO);
            uint64_t dBhi = sdesc(stile_u + ST_B_HI);
            uint64_t dBlo = sdesc(stile_u + ST_B_LO);
#pragma unroll
            for (int kc = 0; kc < 4; kc++)
                mma_bf16_ss(tmem, dAhi + 2 * kc, dBhi + 2 * kc, (it == 0 && kc == 0) ? 0u : 1u);
#pragma unroll
            for (int kc = 0; kc < 4; kc++)
                mma_bf16_ss(tmem, dAlo + 2 * kc, dBhi + 2 * kc, 1u);
#pragma unroll
            for (int kc = 0; kc < 4; kc++)
                mma_bf16_ss(tmem, dAhi + 2 * kc, dBlo + 2 * kc, 1u);
            TCGEN05_COMMIT(sbase + SM_MBAR + 8 * s);
        }
    }

    MBARRIER_WAIT_PARITY(sbase + SM_MBAR, 1);
    MBARRIER_WAIT_PARITY(sbase + SM_MBAR + 8, 1);
    TCGEN05_FENCE_AFTER();

    if (wid < 4) {
        int gm = m0 + wid * 32 + lane;
        float* dst = g_gates + (size_t)gm * NDIM + n0;
#pragma unroll 1
        for (int cb = 0; cb < TILE_N; cb += 32) {
            uint32_t r[32];
            TCGEN05_LD_32X32B_X32(r, tmem + cb);
            TCGEN05_WAIT_LD();
#pragma unroll
            for (int c = 0; c < 32; c += 4) {
                float4 v = make_float4(__uint_as_float(r[c]), __uint_as_float(r[c + 1]),
                                       __uint_as_float(r[c + 2]), __uint_as_float(r[c + 3]));
                *reinterpret_cast<float4*>(dst + cb + c) = v;
            }
        }
        TCGEN05_FENCE_BEFORE();
    }
    __syncthreads();
    if (tid == 0) {
        MBARRIER_INVAL(sbase + SM_MBAR);
        MBARRIER_INVAL(sbase + SM_MBAR + 8);
    }
    __syncthreads();
    if (wid == 0) TCGEN05_DEALLOC(tmem, 256);
#else
    // ================= legacy mma.sync path (compute_103-safe) =================
    // 8 warps in 4(M) x 2(N) grid; warp tile 32 x 128; bf16x3 hi/lo split.
    int warp_m = wid & 3, warp_n = wid >> 2;

    // A fragment per-lane addressing (ldmatrix x4 covering one 16x16 m-frag)
    uint32_t aoff[2], axor[2];
#pragma unroll
    for (int fm = 0; fm < 2; fm++) {
        int arow = warp_m * 32 + fm * 16 + (lane & 15);
        aoff[fm] = (uint32_t)(arow * 128);
        axor[fm] = (uint32_t)((arow & 7) << 4);
    }
    uint32_t asub = (uint32_t)((lane >> 4) << 4);

    // B fragment per-lane addressing (x4 covering two 8-wide n-frags over k=16)
    int brow = warp_n * 128 + (lane & 7) + ((lane >> 4) & 1) * 8;
    uint32_t boff0 = (uint32_t)(brow * 128);
    uint32_t bxor = (uint32_t)((brow & 7) << 4);
    uint32_t bsub = (uint32_t)(((lane >> 3) & 1) << 4);

    float acc[2][16][4];
#pragma unroll
    for (int fm = 0; fm < 2; fm++)
#pragma unroll
        for (int fn = 0; fn < 16; fn++)
#pragma unroll
            for (int j = 0; j < 4; j++) acc[fm][fn][j] = 0.0f;

    // prologue: stage 0
    {
        uint32_t nb = sbase + SM_TILES;
        load_tile_async<128>(g_Ahi, m0, 0, nb + ST_A_HI, tid);
        load_tile_async<128>(g_Alo, m0, 0, nb + ST_A_LO, tid);
        load_tile_async<256>(g_Bhi, n0, 0, nb + ST_B_HI, tid);
        load_tile_async<256>(g_Blo, n0, 0, nb + ST_B_LO, tid);
        CP_COMMIT();
    }

#pragma unroll 1
    for (int it = 0; it < K_ITERS; ++it) {
        int s = it & 1;
        if (it + 1 < K_ITERS) {
            uint32_t nb = sbase + SM_TILES + (uint32_t)((it + 1) & 1) * STAGE_BYTES;
            int k0 = (it + 1) * TILE_K;
            load_tile_async<128>(g_Ahi, m0, k0, nb + ST_A_HI, tid);
            load_tile_async<128>(g_Alo, m0, k0, nb + ST_A_LO, tid);
            load_tile_async<256>(g_Bhi, n0, k0, nb + ST_B_HI, tid);
            load_tile_async<256>(g_Blo, n0, k0, nb + ST_B_LO, tid);
            CP_COMMIT();
            CP_WAIT1();
        } else {
            CP_WAIT0();
        }
        __syncthreads();

        uint32_t sb = sbase + SM_TILES + (uint32_t)s * STAGE_BYTES;
#pragma unroll
        for (int ks = 0; ks < 4; ks++) {
            uint32_t ah[2][4], al[2][4], bb[8][4];
            uint32_t acb = (uint32_t)(ks * 32) + asub;
            uint32_t bcb = (uint32_t)(ks * 32) + bsub;
#pragma unroll
            for (int fm = 0; fm < 2; fm++) {
                LDSM4(ah[fm], sb + ST_A_HI + aoff[fm] + (acb ^ axor[fm]));
                LDSM4(al[fm], sb + ST_A_LO + aoff[fm] + (acb ^ axor[fm]));
            }
#pragma unroll
            for (int p = 0; p < 8; p++)
                LDSM4(bb[p], sb + ST_B_HI + boff0 + (uint32_t)(p * 2048) + (bcb ^ bxor));
            // pass 1: Ahi * Bhi ; pass 2: Alo * Bhi
#pragma unroll
            for (int p = 0; p < 8; p++)
#pragma unroll
                for (int hf = 0; hf < 2; hf++) {
#pragma unroll
                    for (int fm = 0; fm < 2; fm++)
                        MMA16816(acc[fm][2 * p + hf], ah[fm], bb[p][2 * hf], bb[p][2 * hf + 1]);
#pragma unroll
                    for (int fm = 0; fm < 2; fm++)
                        MMA16816(acc[fm][2 * p + hf], al[fm], bb[p][2 * hf], bb[p][2 * hf + 1]);
                }
            // pass 3: Ahi * Blo (reuse bb registers)
#pragma unroll
            for (int p = 0; p < 8; p++)
                LDSM4(bb[p], sb + ST_B_LO + boff0 + (uint32_t)(p * 2048) + (bcb ^ bxor));
#pragma unroll
            for (int p = 0; p < 8; p++)
#pragma unroll
                for (int hf = 0; hf < 2; hf++)
#pragma unroll
                    for (int fm = 0; fm < 2; fm++)
                        MMA16816(acc[fm][2 * p + hf], ah[fm], bb[p][2 * hf], bb[p][2 * hf + 1]);
        }
        __syncthreads();
    }

    // epilogue: write accumulators to g_gates
    {
        int gm0 = m0 + warp_m * 32 + (lane >> 2);
        int gn0 = n0 + warp_n * 128 + (lane & 3) * 2;
#pragma unroll
        for (int fm = 0; fm < 2; fm++) {
#pragma unroll
            for (int fn = 0; fn < 16; fn++) {
                int r0w = gm0 + fm * 16;
                int cc = gn0 + fn * 8;
                float2 v01 = make_float2(acc[fm][fn][0], acc[fm][fn][1]);
                float2 v23 = make_float2(acc[fm][fn][2], acc[fm][fn][3]);
                *reinterpret_cast<float2*>(g_gates + (size_t)r0w * NDIM + cc) = v01;
                *reinterpret_cast<float2*>(g_gates + (size_t)(r0w + 8) * NDIM + cc) = v23;
            }
        }
    }
#endif
}

// ---------------- Kernel 4: LSTM pointwise epilogue ----------------
__global__ void lstm_epi_kernel(const float* __restrict__ c,
                                const float* __restrict__ bi, const float* __restrict__ bf,
                                const float* __restrict__ bo, const float* __restrict__ bc,
                                float* __restrict__ out) {
    size_t gid = (size_t)blockIdx.x * blockDim.x + threadIdx.x;
    size_t e = gid * 4;
    if (e >= (size_t)BDIM * HDIM) return;
    int b = (int)(e >> 11);
    int j = (int)(e & 2047);
    const float* grow = g_gates + (size_t)b * NDIM + j;
    float4 xi = *reinterpret_cast<const float4*>(grow);
    float4 xf = *reinterpret_cast<const float4*>(grow + 2048);
    float4 xo = *reinterpret_cast<const float4*>(grow + 4096);
    float4 xg = *reinterpret_cast<const float4*>(grow + 6144);
    float4 vbi = *reinterpret_cast<const float4*>(bi + j);
    float4 vbf = *reinterpret_cast<const float4*>(bf + j);
    float4 vbo = *reinterpret_cast<const float4*>(bo + j);
    float4 vbc = *reinterpret_cast<const float4*>(bc + j);
    float4 vc  = *reinterpret_cast<const float4*>(c + e);

    const float* ai = (const float*)&xi; const float* af = (const float*)&xf;
    const float* ao = (const float*)&xo; const float* ag = (const float*)&xg;
    const float* pbi = (const float*)&vbi; const float* pbf = (const float*)&vbf;
    const float* pbo = (const float*)&vbo; const float* pbc = (const float*)&vbc;
    const float* pc = (const float*)&vc;

    float4 hout, cout;
    float* ph = (float*)&hout; float* pcc = (float*)&cout;
#pragma unroll
    for (int i = 0; i < 4; i++) {
        float gi = ai[i] + pbi[i];
        float gf = af[i] + pbf[i];
        float go = ao[i] + pbo[i];
        float gg = ag[i] + pbc[i];
        float si = 1.0f / (1.0f + expf(-gi));
        float sf = 1.0f / (1.0f + expf(-gf));
        float so = 1.0f / (1.0f + expf(-go));
        float tg = tanhf(gg);
        float ct = pc[i] * sf + si * tg;
        float ht = so * tanhf(ct);
        ph[i] = ht;
        pcc[i] = ct;
    }
    *reinterpret_cast<float4*>(out + e) = hout;                              // h_t
    *reinterpret_cast<float4*>(out + (size_t)BDIM * HDIM + e) = cout;        // c_t
}

// ---------------- host launch ----------------
extern "C" void kernel_launch(void* const* d_in, const int* in_sizes, int n_in,
                              void* d_out, int out_size) {
    const float* x = (const float*)d_in[0];
    const float* h = (const float*)d_in[1];
    const float* c = (const float*)d_in[2];
    const float* w_xi = (const float*)d_in[3];
    const float* w_xf = (const float*)d_in[4];
    const float* w_xo = (const float*)d_in[5];
    const float* w_xc = (const float*)d_in[6];
    const float* w_hi = (const float*)d_in[7];
    const float* w_hf = (const float*)d_in[8];
    const float* w_ho = (const float*)d_in[9];
    const float* w_hc = (const float*)d_in[10];
    const float* b_i = (const float*)d_in[11];
    const float* b_f = (const float*)d_in[12];
    const float* b_o = (const float*)d_in[13];
    const float* b_c = (const float*)d_in[14];
    float* out = (float*)d_out;

    cudaFuncSetAttribute(gemm_kernel, cudaFuncAttributeMaxDynamicSharedMemorySize, GEMM_SMEM);

    {
        size_t total = (size_t)BDIM * KDIM / 4;
        int blocks = (int)((total + 255) / 256);
        prep_a_kernel<<<blocks, 256>>>(x, h);
    }
    {
        dim3 grid(2048 / 64, 2048 / 32, 8);
        dim3 blk(32, 8);
        prep_w_kernel<<<grid, blk>>>(w_xi, w_xf, w_xo, w_xc, w_hi, w_hf, w_ho, w_hc);
    }
    gemm_kernel<<<1024, 256, GEMM_SMEM>>>();
    {
        size_t total = (size_t)BDIM * HDIM / 4;
        int blocks = (int)((total + 255) / 256);
        lstm_epi_kernel<<<blocks, 256>>>(c, b_i, b_f, b_o, b_c, out);
    }
    (void)in_sizes; (void)n_in; (void)out_size;
}